// round 17
// baseline (speedup 1.0000x reference)
#include <cuda_runtime.h>
#include <cuda_fp16.h>
#include <mma.h>
#include <cstdint>
#include <cstddef>

using namespace nvcuda;

#define BATCH 4
#define SEQ   2048
#define CH    1024

// GEMM tiling (R15/R16-proven): CTA 128x128, 4 warps (2m x 2n), warp 64x64,
// 128 threads, 2 CTAs/SM. Single-fp16. BKC=64, NSTAGE=3.
// R17: persistent CTAs (grid=296) loop over tiles to kill wave tails.
#define NTH 128
#define BKC 64
#define BKP 72                        // padded smem ld (elems) -> 144B rows
#define A_BYTES (128 * BKP * 2)       // 18432 B
#define B_BYTES (128 * BKP * 2)       // 18432 B
#define STAGE_BYTES (A_BYTES + B_BYTES)       // 36864 B
#define NSTAGE 3
#define GEMM_SMEM (NSTAGE * STAGE_BYTES)      // 110592 B (x2 CTAs = 221184)
#define PERSIST 296                   // 148 SMs x 2 CTAs

// ---------------------------------------------------------------------------
// helpers
// ---------------------------------------------------------------------------
__device__ __forceinline__ uint32_t smem_u32(const void* p) {
    uint32_t a;
    asm("{ .reg .u64 t; cvta.to.shared.u64 t, %1; cvt.u32.u64 %0, t; }"
        : "=r"(a) : "l"(p));
    return a;
}

__device__ __forceinline__ void cp_async16(void* dst, const void* src) {
    uint32_t d = smem_u32(dst);
    asm volatile("cp.async.cg.shared.global [%0], [%1], 16;"
                 :: "r"(d), "l"(src) : "memory");
}
__device__ __forceinline__ void cp_commit() {
    asm volatile("cp.async.commit_group;" ::: "memory");
}
template <int N>
__device__ __forceinline__ void cp_wait_group() {
    asm volatile("cp.async.wait_group %0;" :: "n"(N) : "memory");
}

__device__ __forceinline__ uint32_t pack_h2(float a, float b) {
    __half2 h = __floats2half2_rn(a, b);
    return *reinterpret_cast<uint32_t*>(&h);
}

// ---------------------------------------------------------------------------
// scratch
// ---------------------------------------------------------------------------
#define NXE ((size_t)BATCH * SEQ * CH)
#define NWE ((size_t)CH * CH)
#define NSE ((size_t)BATCH * SEQ * SEQ)

__device__ __align__(1024) __half g_xq[NXE], g_xk[NXE], g_xv[NXE];
__device__ __align__(1024) __half g_wq[NWE], g_wk[NWE], g_wv[NWE];
__device__ __align__(1024) __half g_Q[NXE],  g_K[NXE];
__device__ __align__(1024) __half g_Vt[NXE];
__device__ __align__(1024) float  g_Sf[NSE];
__device__ __align__(1024) __half g_S[NSE];

// ---------------------------------------------------------------------------
// fused packing: 3 inputs (4096 blocks) + 3 weights (512 blocks), single fp16
// ---------------------------------------------------------------------------
struct PackJob {
    const float* srcX;  __half* xh;
    const float* srcW;  __half* wh;
};

__global__ void __launch_bounds__(256)
pack_all(PackJob j0, PackJob j1, PackJob j2)
{
    const PackJob& j = (blockIdx.y == 0) ? j0 : (blockIdx.y == 1) ? j1 : j2;
    const float* src;
    __half* dst;
    size_t base;
    if (blockIdx.x < 4096) {
        src = j.srcX; dst = j.xh;
        base = ((size_t)blockIdx.x * 256 + threadIdx.x) * 8;
    } else {
        src = j.srcW; dst = j.wh;
        base = ((size_t)(blockIdx.x - 4096) * 256 + threadIdx.x) * 8;
    }
    float4 f0 = *reinterpret_cast<const float4*>(src + base);
    float4 f1 = *reinterpret_cast<const float4*>(src + base + 4);
    uint4 H;
    H.x = pack_h2(f0.x, f0.y);
    H.y = pack_h2(f0.z, f0.w);
    H.z = pack_h2(f1.x, f1.y);
    H.w = pack_h2(f1.z, f1.w);
    *reinterpret_cast<uint4*>((char*)dst + base * 2) = H;
}

// ---------------------------------------------------------------------------
// softmax over rows of S fp32 [B*S][2048] -> single fp16 row-major
// ---------------------------------------------------------------------------
__global__ void __launch_bounds__(256)
softmax_pack(const float* __restrict__ S, __half* __restrict__ Dh)
{
    __shared__ float red[32];
    int rowG = blockIdx.x, t = threadIdx.x;
    const float* row = S + (size_t)rowG * SEQ;
    float4 a = *reinterpret_cast<const float4*>(row + t * 8);
    float4 b2 = *reinterpret_cast<const float4*>(row + t * 8 + 4);
    float v[8] = {a.x, a.y, a.z, a.w, b2.x, b2.y, b2.z, b2.w};

    float m = v[0];
#pragma unroll
    for (int i = 1; i < 8; i++) m = fmaxf(m, v[i]);
#pragma unroll
    for (int o = 16; o > 0; o >>= 1)
        m = fmaxf(m, __shfl_xor_sync(0xffffffffu, m, o));
    if ((t & 31) == 0) red[t >> 5] = m;
    __syncthreads();
    if (t < 32) {
        float x = (t < 8) ? red[t] : -3.4e38f;
#pragma unroll
        for (int o = 4; o > 0; o >>= 1) x = fmaxf(x, __shfl_xor_sync(0xffffffffu, x, o));
        if (t == 0) red[0] = x;
    }
    __syncthreads();
    m = red[0];
    __syncthreads();

    float sum = 0.0f;
#pragma unroll
    for (int i = 0; i < 8; i++) { v[i] = __expf(v[i] - m); sum += v[i]; }
#pragma unroll
    for (int o = 16; o > 0; o >>= 1) sum += __shfl_xor_sync(0xffffffffu, sum, o);
    if ((t & 31) == 0) red[t >> 5] = sum;
    __syncthreads();
    if (t < 32) {
        float x = (t < 8) ? red[t] : 0.0f;
#pragma unroll
        for (int o = 4; o > 0; o >>= 1) x += __shfl_xor_sync(0xffffffffu, x, o);
        if (t == 0) red[0] = x;
    }
    __syncthreads();
    float inv = 1.0f / red[0];

    uint4 H;
    H.x = pack_h2(v[0] * inv, v[1] * inv);
    H.y = pack_h2(v[2] * inv, v[3] * inv);
    H.z = pack_h2(v[4] * inv, v[5] * inv);
    H.w = pack_h2(v[6] * inv, v[7] * inv);
    size_t e = (size_t)rowG * SEQ + t * 8;
    *reinterpret_cast<uint4*>((char*)Dh + e * 2) = H;
}

// ---------------------------------------------------------------------------
// GEMM mainloop (R15-proven): fills acc[4][4] for one 128x128 tile.
// ---------------------------------------------------------------------------
__device__ __forceinline__ void gemm_mainloop(
    char* smem, const __half* __restrict__ Ahb, const __half* __restrict__ Bhb,
    int K, wmma::fragment<wmma::accumulator, 16, 16, 16, float> (&acc)[4][4],
    int wm, int wn)
{
    const int tid = threadIdx.x;
    const int nK = K / BKC;

    auto load_stage = [&](int s, int c) {
        char* st = smem + s * STAGE_BYTES;
        const int k0 = c * BKC;
#pragma unroll
        for (int i = 0; i < 8; i++) {
            int job = tid + i * NTH;
            int r = job >> 3, seg = job & 7;
            size_t goff = (size_t)r * K + k0 + seg * 8;
            uint32_t soff = (uint32_t)r * (BKP * 2) + seg * 16;
            cp_async16(st + soff,           Ahb + goff);
            cp_async16(st + A_BYTES + soff, Bhb + goff);
        }
    };

#pragma unroll
    for (int i = 0; i < 4; i++)
#pragma unroll
        for (int j = 0; j < 4; j++) wmma::fill_fragment(acc[i][j], 0.0f);

#pragma unroll
    for (int s = 0; s < NSTAGE; s++) { load_stage(s, s); cp_commit(); }

    for (int c = 0; c < nK; c++) {
        cp_wait_group<NSTAGE - 1>();
        __syncthreads();

        const char* st = smem + (c % NSTAGE) * STAGE_BYTES;
        const __half* As = (const __half*)st;
        const __half* Bs = (const __half*)(st + A_BYTES);

#pragma unroll
        for (int ks = 0; ks < 4; ks++) {
            wmma::fragment<wmma::matrix_a, 16, 16, 16, __half, wmma::row_major> fa[4];
#pragma unroll
            for (int i = 0; i < 4; i++)
                wmma::load_matrix_sync(fa[i], As + (wm + i * 16) * BKP + ks * 16, BKP);
#pragma unroll
            for (int j = 0; j < 4; j++) {
                wmma::fragment<wmma::matrix_b, 16, 16, 16, __half, wmma::col_major> fb;
                wmma::load_matrix_sync(fb, Bs + (wn + j * 16) * BKP + ks * 16, BKP);
#pragma unroll
                for (int i = 0; i < 4; i++)
                    wmma::mma_sync(acc[i][j], fa[i], fb, acc[i][j]);
            }
        }
        __syncthreads();
        if (c + NSTAGE < nK) load_stage(c % NSTAGE, c + NSTAGE);
        cp_commit();
    }
    cp_wait_group<0>();
    __syncthreads();
}

// ---------------------------------------------------------------------------
// persistent direct-epilogue GEMM (no bias): C = alpha * A B^T
// grid = PERSIST; tiles indexed bx fastest (A-panel L2 reuse), then by, bz.
// ---------------------------------------------------------------------------
__global__ void __launch_bounds__(NTH, 2)
tc_gemm_direct(const __half* __restrict__ Ah, const __half* __restrict__ Bh,
               int K, size_t aStride, size_t bStride, float alpha,
               float* __restrict__ outF, int ldC, size_t cStride,
               int nbx, int nTiles)
{
    extern __shared__ char smem[];
    const int wid = threadIdx.x >> 5;
    const int wm = (wid & 1) * 64, wn = (wid >> 1) * 64;

    for (int t = blockIdx.x; t < nTiles; t += PERSIST) {
        int bx = t % nbx;
        int rem = t / nbx;
        int by = rem & 15;                    // nby = 16 for both uses
        int bz = rem >> 4;
        const int m0 = by * 128, n0 = bx * 128;

        wmma::fragment<wmma::accumulator, 16, 16, 16, float> acc[4][4];
        gemm_mainloop(smem,
                      Ah + (size_t)bz * aStride + (size_t)m0 * K,
                      Bh + (size_t)bz * bStride + (size_t)n0 * K,
                      K, acc, wm, wn);

        float* base = outF + (size_t)bz * cStride;
#pragma unroll
        for (int i = 0; i < 4; i++)
#pragma unroll
            for (int j = 0; j < 4; j++) {
#pragma unroll
                for (int e = 0; e < acc[i][j].num_elements; e++)
                    acc[i][j].x[e] *= alpha;
                wmma::store_matrix_sync(
                    base + (size_t)(m0 + wm + i * 16) * ldC + n0 + wn + j * 16,
                    acc[i][j], ldC, wmma::mem_row_major);
            }
        // no smem use in epilogue; next tile's mainloop syncs before reuse
    }
}

// ---------------------------------------------------------------------------
// persistent fused projections. tile index: bx (8) fastest, by (64), z (3).
// z = {0:Q, 1:K, 2:V}. Q/K: bias + fp16 row-major. V: bias + fp16 transposed.
// ---------------------------------------------------------------------------
struct ProjSet {
    const __half *a, *b;
    const float* bias;
    __half* outH;
    int transposed;
};

__global__ void __launch_bounds__(NTH, 2)
proj_gemm(ProjSet p0, ProjSet p1, ProjSet p2)
{
    extern __shared__ char smem[];
    const int tid = threadIdx.x;
    const int wid = tid >> 5, lane = tid & 31;
    const int wm = (wid & 1) * 64, wn = (wid >> 1) * 64;
    const int nTiles = 8 * 64 * 3;

    for (int t = blockIdx.x; t < nTiles; t += PERSIST) {
        int bx = t & 7;
        int rem = t >> 3;
        int by = rem & 63;
        int z = rem >> 6;
        const ProjSet& p = (z == 0) ? p0 : (z == 1) ? p1 : p2;
        const int m0 = by * 128, n0 = bx * 128;

        wmma::fragment<wmma::accumulator, 16, 16, 16, float> acc[4][4];
        gemm_mainloop(smem,
                      p.a + (size_t)m0 * CH,
                      p.b + (size_t)n0 * CH,
                      CH, acc, wm, wn);

        if (!p.transposed) {
            float* Cs = (float*)smem;
#pragma unroll
            for (int i = 0; i < 4; i++)
#pragma unroll
                for (int j = 0; j < 4; j++)
                    wmma::store_matrix_sync(Cs + (wm + i * 16) * 128 + wn + j * 16,
                                            acc[i][j], 128, wmma::mem_row_major);
            __syncthreads();
#pragma unroll
            for (int it = 0; it < 32; it++) {
                int g = tid + it * NTH;       // 4096 float4 groups
                int r = g >> 5, c4 = (g & 31) * 4;
                float4 v = *reinterpret_cast<const float4*>(Cs + r * 128 + c4);
                float o0 = v.x + p.bias[n0 + c4 + 0];
                float o1 = v.y + p.bias[n0 + c4 + 1];
                float o2 = v.z + p.bias[n0 + c4 + 2];
                float o3 = v.w + p.bias[n0 + c4 + 3];
                uint2 H;
                H.x = pack_h2(o0, o1);
                H.y = pack_h2(o2, o3);
                size_t e = (size_t)(m0 + r) * CH + n0 + c4;
                *reinterpret_cast<uint2*>((char*)p.outH + e * 2) = H;
            }
        } else {
            float* Cs = (float*)smem;
#pragma unroll
            for (int i = 0; i < 4; i++)
#pragma unroll
                for (int j = 0; j < 4; j++)
                    wmma::store_matrix_sync(Cs + (wm + i * 16) * 132 + wn + j * 16,
                                            acc[i][j], 132, wmma::mem_row_major);
            __syncthreads();

            int b = m0 >> 11;
            int s0 = m0 & 2047;
#pragma unroll
            for (int rr = 0; rr < 32; rr++) {
                int c = wid * 32 + rr;
                float bv = p.bias[n0 + c];
                __half* dst = p.outH + ((size_t)b * CH + n0 + c) * SEQ + s0;
#pragma unroll
                for (int k = 0; k < 4; k++) {
                    int s = k * 32 + lane;
                    float val = Cs[s * 132 + c] + bv;
                    dst[s] = __float2half_rn(val);
                }
            }
        }
        __syncthreads();   // epilogue reads done before next tile's loads
    }
}

// ---------------------------------------------------------------------------
extern "C" void kernel_launch(void* const* d_in, const int* in_sizes, int n_in,
                              void* d_out, int out_size)
{
    const float* query = (const float*)d_in[0];
    const float* key   = (const float*)d_in[1];
    const float* value = (const float*)d_in[2];
    const float* Wq    = (const float*)d_in[3];
    const float* bq    = (const float*)d_in[4];
    const float* Wk    = (const float*)d_in[5];
    const float* bk    = (const float*)d_in[6];
    const float* Wv    = (const float*)d_in[7];
    const float* bv    = (const float*)d_in[8];
    float* out = (float*)d_out;

    cudaFuncSetAttribute(tc_gemm_direct, cudaFuncAttributeMaxDynamicSharedMemorySize,
                         GEMM_SMEM);
    cudaFuncSetAttribute(proj_gemm, cudaFuncAttributeMaxDynamicSharedMemorySize,
                         GEMM_SMEM);

    __half *xq, *xk, *xv, *wq, *wk, *wv, *Q, *K, *Vt, *S;
    float *Sf;
    cudaGetSymbolAddress((void**)&xq, g_xq);
    cudaGetSymbolAddress((void**)&xk, g_xk);
    cudaGetSymbolAddress((void**)&xv, g_xv);
    cudaGetSymbolAddress((void**)&wq, g_wq);
    cudaGetSymbolAddress((void**)&wk, g_wk);
    cudaGetSymbolAddress((void**)&wv, g_wv);
    cudaGetSymbolAddress((void**)&Q, g_Q);
    cudaGetSymbolAddress((void**)&K, g_K);
    cudaGetSymbolAddress((void**)&Vt, g_Vt);
    cudaGetSymbolAddress((void**)&Sf, g_Sf);
    cudaGetSymbolAddress((void**)&S, g_S);

    // launch #1: fused packing
    PackJob jq = {query, xq, Wq, wq};
    PackJob jk = {key,   xk, Wk, wk};
    PackJob jv = {value, xv, Wv, wv};
    pack_all<<<dim3(4608, 3), 256>>>(jq, jk, jv);

    // launch #2: persistent fused Q/K/V projections (1536 tiles on 296 CTAs)
    ProjSet pQ = {xq, wq, bq, Q,  0};
    ProjSet pK = {xk, wk, bk, K,  0};
    ProjSet pV = {xv, wv, bv, Vt, 1};
    proj_gemm<<<PERSIST, NTH, GEMM_SMEM>>>(pQ, pK, pV);

    // launch #3: scores = Q K^T / 32 (1024 tiles: nbx=16, nby=16, nz=4)
    tc_gemm_direct<<<PERSIST, NTH, GEMM_SMEM>>>(
        Q, K, CH, (size_t)SEQ * CH, (size_t)SEQ * CH, 1.0f / 32.0f,
        Sf, SEQ, (size_t)SEQ * SEQ, 16, 16 * 16 * 4);

    // launch #4: softmax + fp16 pack
    softmax_pack<<<BATCH * SEQ, 256>>>(Sf, S);

    // launch #5: out = attn @ V (512 tiles: nbx=8, nby=16, nz=4)
    tc_gemm_direct<<<PERSIST, NTH, GEMM_SMEM>>>(
        S, Vt, SEQ, (size_t)SEQ * SEQ, (size_t)CH * SEQ, 1.0f,
        out, CH, (size_t)SEQ * CH, 8, 8 * 16 * 4);
}